// round 1
// baseline (speedup 1.0000x reference)
#include <cuda_runtime.h>
#include <math.h>

// Problem constants (fixed shapes)
#define NB 8192
#define NE 512
#define NT 32

#define TM 64          // rows (samples) per tile
#define TN 64          // h-columns per chunk
#define KT 16          // k-tile depth
#define MAXTILES (NB / TM + NT)   // 160 upper bound

// ---- device scratch (no allocations allowed) ----
__device__ int d_is64;
__device__ int d_counts[NT];
__device__ int d_cursor[NT];
__device__ int d_perm[NB];
__device__ int d_tile_tissue[MAXTILES];
__device__ int d_tile_start[MAXTILES];
__device__ int d_tile_rows[MAXTILES];
__device__ int d_ntiles;

// ------------------------------------------------------------------
// Kernel 1: detect int64 vs int32 tissue_vector layout + zero counts.
// Reads only the first NB int32 words (safe for both layouts).
// int64 layout: odd words are high halves == 0 (values in [0,32)).
// int32 layout: odd words are tissue values at odd indices; all-zero
// has probability ~ (1/32)^4096 ~ 0.
// ------------------------------------------------------------------
__global__ void detect_kernel(const int* tv32) {
    __shared__ int sor[256];
    int acc = 0;
    for (int i = threadIdx.x; i < NB / 2; i += 256)
        acc |= tv32[2 * i + 1];
    sor[threadIdx.x] = acc;
    __syncthreads();
    for (int s = 128; s > 0; s >>= 1) {
        if (threadIdx.x < s) sor[threadIdx.x] |= sor[threadIdx.x + s];
        __syncthreads();
    }
    if (threadIdx.x == 0) d_is64 = (sor[0] == 0) ? 1 : 0;
    if (threadIdx.x < NT) d_counts[threadIdx.x] = 0;
}

__device__ __forceinline__ int load_tissue(const void* tv, int b, int is64) {
    if (is64) return (int)((const long long*)tv)[b];
    return ((const int*)tv)[b];
}

// Kernel 2: histogram of tissues
__global__ void hist_kernel(const void* tv) {
    int b = blockIdx.x * blockDim.x + threadIdx.x;
    if (b < NB) {
        int t = load_tissue(tv, b, d_is64);
        atomicAdd(&d_counts[t], 1);
    }
}

// Kernel 3: prefix sum + tile plan (single thread; T=32 trivial)
__global__ void plan_kernel() {
    int off = 0, nt = 0;
    for (int t = 0; t < NT; t++) {
        int c = d_counts[t];
        d_cursor[t] = off;
        for (int s = 0; s < c; s += TM) {
            d_tile_tissue[nt] = t;
            d_tile_start[nt]  = off + s;
            d_tile_rows[nt]   = (c - s) < TM ? (c - s) : TM;
            nt++;
        }
        off += c;
    }
    d_ntiles = nt;
}

// Kernel 4: scatter permutation (order within tissue is arbitrary;
// outputs are per-sample so the result is still deterministic)
__global__ void scatter_kernel(const void* tv) {
    int b = blockIdx.x * blockDim.x + threadIdx.x;
    if (b < NB) {
        int t = load_tissue(tv, b, d_is64);
        int pos = atomicAdd(&d_cursor[t], 1);
        d_perm[pos] = b;
    }
}

// ------------------------------------------------------------------
// Kernel 5: fused grouped GEMM + GELU + W2 reduce + softplus
// One CTA per (tissue, 64-sample) tile. 256 threads (16x16),
// each computes a 4x4 fragment of the 64x64 h-subtile per n-chunk.
// ------------------------------------------------------------------
__global__ void __launch_bounds__(256)
gemm_kernel(const float* __restrict__ g,
            const float* __restrict__ W1,
            const float* __restrict__ b1,
            const float* __restrict__ W2,
            const float* __restrict__ b2,
            float* __restrict__ out)
{
    int tile = blockIdx.x;
    if (tile >= d_ntiles) return;

    const int t     = d_tile_tissue[tile];
    const int start = d_tile_start[tile];
    const int rows  = d_tile_rows[tile];

    __shared__ float Gs[KT][TM + 4];   // +4 pad: eases STS conflicts, keeps 16B align
    __shared__ float Ws[KT][TN];
    __shared__ int   srow[TM];
    __shared__ float red[TM][17];

    const int tid = threadIdx.x;
    const int tx = tid & 15;
    const int ty = tid >> 4;

    if (tid < TM) {
        int m = tid < rows ? tid : (rows - 1);   // clamp; stores are guarded later
        srow[tid] = d_perm[start + m];
    }
    __syncthreads();

    const float* Wt = W1 + (size_t)t * NE * NE;
    float accy[4] = {0.f, 0.f, 0.f, 0.f};

    for (int n0 = 0; n0 < NE; n0 += TN) {
        float c[4][4];
        #pragma unroll
        for (int i = 0; i < 4; i++)
            #pragma unroll
            for (int j = 0; j < 4; j++)
                c[i][j] = 0.f;

        for (int k0 = 0; k0 < NE; k0 += KT) {
            // load G tile (transposed into Gs[k][m])
            {
                int m  = tid >> 2;
                int kq = (tid & 3) << 2;
                const float4 v = *(const float4*)(g + (size_t)srow[m] * NE + k0 + kq);
                Gs[kq + 0][m] = v.x;
                Gs[kq + 1][m] = v.y;
                Gs[kq + 2][m] = v.z;
                Gs[kq + 3][m] = v.w;
            }
            // load W1 tile
            {
                int k  = tid >> 4;
                int nq = (tid & 15) << 2;
                *(float4*)&Ws[k][nq] =
                    *(const float4*)(Wt + (size_t)(k0 + k) * NE + n0 + nq);
            }
            __syncthreads();

            #pragma unroll
            for (int k = 0; k < KT; k++) {
                float4 a  = *(const float4*)&Gs[k][ty << 2];
                float4 bv = *(const float4*)&Ws[k][tx << 2];
                float av[4] = {a.x, a.y, a.z, a.w};
                float bw[4] = {bv.x, bv.y, bv.z, bv.w};
                #pragma unroll
                for (int i = 0; i < 4; i++)
                    #pragma unroll
                    for (int j = 0; j < 4; j++)
                        c[i][j] = fmaf(av[i], bw[j], c[i][j]);
            }
            __syncthreads();
        }

        // fused epilogue for this n-chunk: +b1, exact GELU, *W2, accumulate
        #pragma unroll
        for (int j = 0; j < 4; j++) {
            int n = n0 + (tx << 2) + j;
            float b1v = __ldg(&b1[t * NE + n]);
            float w2v = __ldg(&W2[t * NE + n]);
            #pragma unroll
            for (int i = 0; i < 4; i++) {
                float h  = c[i][j] + b1v;
                float ge = 0.5f * h * (1.0f + erff(h * 0.70710678118654752f));
                accy[i] = fmaf(ge, w2v, accy[i]);
            }
        }
    }

    // reduce partial y across the 16 tx columns
    #pragma unroll
    for (int i = 0; i < 4; i++)
        red[(ty << 2) + i][tx] = accy[i];
    __syncthreads();

    if (tid < TM) {
        float s = 0.f;
        #pragma unroll
        for (int j = 0; j < 16; j++) s += red[tid][j];
        s += __ldg(&b2[t]);
        // stable softplus: log1p(exp(x)) = max(x,0) + log1p(exp(-|x|))
        float y = fmaxf(s, 0.f) + log1pf(expf(-fabsf(s)));
        if (tid < rows) out[srow[tid]] = y;
    }
}

// ------------------------------------------------------------------
extern "C" void kernel_launch(void* const* d_in, const int* in_sizes, int n_in,
                              void* d_out, int out_size)
{
    const float* g   = (const float*)d_in[0];
    const void*  tv  = d_in[1];
    const float* W1  = (const float*)d_in[2];
    const float* b1  = (const float*)d_in[3];
    const float* W2  = (const float*)d_in[4];
    const float* b2  = (const float*)d_in[5];
    float* out = (float*)d_out;

    detect_kernel<<<1, 256>>>((const int*)tv);
    hist_kernel<<<(NB + 255) / 256, 256>>>(tv);
    plan_kernel<<<1, 1>>>();
    scatter_kernel<<<(NB + 255) / 256, 256>>>(tv);
    gemm_kernel<<<MAXTILES, 256>>>(g, W1, b1, W2, b2, out);
}

// round 3
// speedup vs baseline: 1.3622x; 1.3622x over previous
#include <cuda_runtime.h>
#include <cuda_bf16.h>
#include <math.h>
#include <stdint.h>

#define NB 8192
#define NE 512
#define NT 32
#define TM 128
#define MAXTILES (NB/TM + NT)   // 96

// ---------------- device scratch (static, no allocations) ----------------
__device__ int d_is64;
__device__ int d_counts[NT];
__device__ int d_cursor[NT];
__device__ int d_perm[NB];
__device__ int d_tile_tissue[MAXTILES];
__device__ int d_tile_start[MAXTILES];
__device__ int d_tile_rows[MAXTILES];
__device__ int d_ntiles;

__device__ __nv_bfloat16 d_Ghi[NB * NE];
__device__ __nv_bfloat16 d_Glo[NB * NE];
__device__ __nv_bfloat16 d_WhiT[(size_t)NT * NE * NE];   // [t][n][k]
__device__ __nv_bfloat16 d_WloT[(size_t)NT * NE * NE];

// ---------------- PTX helpers (all sm_80-level, compile under compute_103) --
__device__ __forceinline__ uint32_t smem_u32(const void* p) {
    uint32_t a;
    asm("{ .reg .u64 t; cvta.to.shared.u64 t, %1; cvt.u32.u64 %0, t; }"
        : "=r"(a) : "l"(p));
    return a;
}
#define CP16(dst, src) \
    asm volatile("cp.async.cg.shared.global [%0], [%1], 16;" \
                 :: "r"(dst), "l"(src) : "memory")
#define CP_COMMIT() asm volatile("cp.async.commit_group;" ::: "memory")
#define CP_WAIT1()  asm volatile("cp.async.wait_group 1;" ::: "memory")
#define CP_WAIT0()  asm volatile("cp.async.wait_group 0;" ::: "memory")

__device__ __forceinline__ void ldsm4(uint32_t r[4], uint32_t addr) {
    asm volatile("ldmatrix.sync.aligned.m8n8.x4.shared.b16 {%0,%1,%2,%3}, [%4];"
                 : "=r"(r[0]), "=r"(r[1]), "=r"(r[2]), "=r"(r[3]) : "r"(addr));
}
__device__ __forceinline__ void mma16816(float d[4], const uint32_t a[4],
                                         const uint32_t b[2]) {
    asm volatile(
        "mma.sync.aligned.m16n8k16.row.col.f32.bf16.bf16.f32 "
        "{%0,%1,%2,%3}, {%4,%5,%6,%7}, {%8,%9}, {%0,%1,%2,%3};"
        : "+f"(d[0]), "+f"(d[1]), "+f"(d[2]), "+f"(d[3])
        : "r"(a[0]), "r"(a[1]), "r"(a[2]), "r"(a[3]), "r"(b[0]), "r"(b[1]));
}
__device__ __forceinline__ unsigned pack2(__nv_bfloat16 a, __nv_bfloat16 b) {
    return (unsigned)__bfloat16_as_ushort(a) | ((unsigned)__bfloat16_as_ushort(b) << 16);
}

// ---------------- grouping kernels (proven in R1) ----------------
__global__ void detect_kernel(const int* tv32) {
    __shared__ int sor[256];
    int acc = 0;
    for (int i = threadIdx.x; i < NB / 2; i += 256) acc |= tv32[2 * i + 1];
    sor[threadIdx.x] = acc;
    __syncthreads();
    for (int s = 128; s > 0; s >>= 1) {
        if (threadIdx.x < s) sor[threadIdx.x] |= sor[threadIdx.x + s];
        __syncthreads();
    }
    if (threadIdx.x == 0) d_is64 = (sor[0] == 0) ? 1 : 0;
    if (threadIdx.x < NT) d_counts[threadIdx.x] = 0;
}
__device__ __forceinline__ int load_tissue(const void* tv, int b, int is64) {
    if (is64) return (int)((const long long*)tv)[b];
    return ((const int*)tv)[b];
}
__global__ void hist_kernel(const void* tv) {
    int b = blockIdx.x * blockDim.x + threadIdx.x;
    if (b < NB) atomicAdd(&d_counts[load_tissue(tv, b, d_is64)], 1);
}
__global__ void plan_kernel() {
    int off = 0, nt = 0;
    for (int t = 0; t < NT; t++) {
        int c = d_counts[t];
        d_cursor[t] = off;
        for (int s = 0; s < c; s += TM) {
            d_tile_tissue[nt] = t;
            d_tile_start[nt]  = off + s;
            d_tile_rows[nt]   = (c - s) < TM ? (c - s) : TM;
            nt++;
        }
        off += c;
    }
    d_ntiles = nt;
}
__global__ void scatter_kernel(const void* tv) {
    int b = blockIdx.x * blockDim.x + threadIdx.x;
    if (b < NB) {
        int t = load_tissue(tv, b, d_is64);
        d_perm[atomicAdd(&d_cursor[t], 1)] = b;
    }
}

// ---------------- prep: fp32 -> bf16 hi/lo ----------------
__global__ void prep_g(const float* __restrict__ g) {
    int i = blockIdx.x * 256 + threadIdx.x;
    float4 v = ((const float4*)g)[i];
    float x[4] = {v.x, v.y, v.z, v.w};
    __nv_bfloat16 hb[4], lb[4];
#pragma unroll
    for (int j = 0; j < 4; j++) {
        hb[j] = __float2bfloat16(x[j]);
        lb[j] = __float2bfloat16(x[j] - __bfloat162float(hb[j]));
    }
    ((uint2*)d_Ghi)[i] = make_uint2(pack2(hb[0], hb[1]), pack2(hb[2], hb[3]));
    ((uint2*)d_Glo)[i] = make_uint2(pack2(lb[0], lb[1]), pack2(lb[2], lb[3]));
}

__global__ void prep_w(const float* __restrict__ W1) {
    int t  = blockIdx.x >> 3;
    int n0 = (blockIdx.x & 7) * 64;
    __shared__ float st[64][65];
    const size_t tb = (size_t)t * NE * NE;
    for (int kb = 0; kb < 8; kb++) {
        int k0 = kb * 64;
#pragma unroll
        for (int rr = 0; rr < 4; rr++) {
            int idx = threadIdx.x + rr * 256;
            int k = idx >> 4;
            int nq = (idx & 15) << 2;
            float4 v = *(const float4*)(W1 + tb + (size_t)(k0 + k) * NE + n0 + nq);
            st[nq + 0][k] = v.x; st[nq + 1][k] = v.y;
            st[nq + 2][k] = v.z; st[nq + 3][k] = v.w;
        }
        __syncthreads();
        {
            int n  = threadIdx.x >> 2;
            int kq = (threadIdx.x & 3) << 4;
            unsigned hw[8], lw[8];
#pragma unroll
            for (int j = 0; j < 16; j += 2) {
                float x0 = st[n][kq + j], x1 = st[n][kq + j + 1];
                __nv_bfloat16 h0 = __float2bfloat16(x0), h1 = __float2bfloat16(x1);
                __nv_bfloat16 l0 = __float2bfloat16(x0 - __bfloat162float(h0));
                __nv_bfloat16 l1 = __float2bfloat16(x1 - __bfloat162float(h1));
                hw[j >> 1] = pack2(h0, h1);
                lw[j >> 1] = pack2(l0, l1);
            }
            size_t oo = tb + (size_t)(n0 + n) * NE + k0 + kq;
            *(uint4*)(d_WhiT + oo)     = make_uint4(hw[0], hw[1], hw[2], hw[3]);
            *(uint4*)(d_WhiT + oo + 8) = make_uint4(hw[4], hw[5], hw[6], hw[7]);
            *(uint4*)(d_WloT + oo)     = make_uint4(lw[0], lw[1], lw[2], lw[3]);
            *(uint4*)(d_WloT + oo + 8) = make_uint4(lw[4], lw[5], lw[6], lw[7]);
        }
        __syncthreads();
    }
}

// ---------------- mma.sync fused GEMM ----------------
// smem: srow 0..512 | b1s 512..2560 | w2s 2560..4608 | red 4608..5632 |
// stage bufs @6144, 2 x 49152 (Ahi 8K, Alo 8K, Bhi 16K, Blo 16K)
#define SM_SROW 0
#define SM_B1   512
#define SM_W2   2560
#define SM_RED  4608
#define SM_ST   6144
#define BUFSZ   49152
#define SM_TOTAL (SM_ST + 2*BUFSZ)

__device__ __forceinline__ void stage_load(
    uint32_t bufb, int s, int tid, size_t aoff, size_t wbase)
{
    const int k0 = s * 32;
    {   // A: 128 rows x 32 k ; thread -> row=tid>>1, chunkpair=(tid&1)*2
        int row = tid >> 1;
        int sw  = (row >> 1) & 3;
        uint32_t drow = bufb + row * 64;
        int cp = (tid & 1) * 2;
        const __nv_bfloat16* ghi = d_Ghi + aoff + k0;
        const __nv_bfloat16* glo = d_Glo + aoff + k0;
#pragma unroll
        for (int c = cp; c < cp + 2; c++) {
            uint32_t d = drow + ((c ^ sw) << 4);
            CP16(d, ghi + c * 8);
            CP16(d + 8192, glo + c * 8);
        }
    }
    {   // B: 256 rows x 32 k ; thread -> row=tid, 4 chunks
        int sw = (tid >> 1) & 3;
        uint32_t drow = bufb + 16384 + tid * 64;
        const __nv_bfloat16* whi = d_WhiT + wbase + k0;
        const __nv_bfloat16* wlo = d_WloT + wbase + k0;
#pragma unroll
        for (int c = 0; c < 4; c++) {
            uint32_t d = drow + ((c ^ sw) << 4);
            CP16(d, whi + c * 8);
            CP16(d + 16384, wlo + c * 8);
        }
    }
}

__global__ void __launch_bounds__(256, 1)
gemm_mma(const float* __restrict__ b1g, const float* __restrict__ W2g,
         const float* __restrict__ b2g, float* __restrict__ out)
{
    extern __shared__ char smem[];
    const uint32_t sb = smem_u32(smem);
    const int tid = threadIdx.x, wid = tid >> 5, lane = tid & 31;
    const int wm = wid & 3, wn = wid >> 2;

    const int tile = blockIdx.x;
    if (tile >= d_ntiles) return;
    const int t = d_tile_tissue[tile];
    const int start = d_tile_start[tile];
    const int rows  = d_tile_rows[tile];

    int*   srow_sm = (int*)(smem + SM_SROW);
    float* b1s = (float*)(smem + SM_B1);
    float* w2s = (float*)(smem + SM_W2);
    float* red = (float*)(smem + SM_RED);

    if (tid < TM) {
        int m = tid < rows ? tid : rows - 1;
        srow_sm[tid] = d_perm[start + m];
    }
    for (int i = tid; i < NE; i += 256) {
        b1s[i] = b1g[t * NE + i];
        w2s[i] = W2g[t * NE + i];
    }
    __syncthreads();

    // stage-load per-thread constants
    const size_t aoff = (size_t)srow_sm[tid >> 1] * NE;
    const size_t wb = (size_t)t * NE * NE;

    // ldmatrix per-lane constants
    const int rA  = lane & 15;
    const int cbA = lane >> 4;
    const int swA = (rA >> 1) & 3;
    const uint32_t preA = (uint32_t)(wm * 32 + rA) * 64;

    const int rB  = (lane & 7) + ((lane >> 4) & 1) * 8;
    const int cbB = (lane >> 3) & 1;
    const int swB = ((lane & 7) >> 1) & 3;
    const uint32_t preBh = 16384u + (uint32_t)(wn * 128 + rB) * 64;
    const uint32_t preBl = preBh + 16384u;

    const uint32_t ST = sb + SM_ST;

    float acc[2][16][4];
    float ya[2][2] = {{0.f, 0.f}, {0.f, 0.f}};

    for (int nc = 0; nc < 2; nc++) {
        const size_t wbase = wb + (size_t)(nc * 256 + tid) * NE;
#pragma unroll
        for (int mt = 0; mt < 2; mt++)
#pragma unroll
            for (int j = 0; j < 16; j++)
#pragma unroll
                for (int q = 0; q < 4; q++) acc[mt][j][q] = 0.f;

        stage_load(ST, 0, tid, aoff, wbase);
        CP_COMMIT();

        for (int s = 0; s < 16; s++) {
            if (s < 15) {
                stage_load(ST + ((s + 1) & 1) * BUFSZ, s + 1, tid, aoff, wbase);
                CP_COMMIT();
                CP_WAIT1();
            } else {
                CP_WAIT0();
            }
            __syncthreads();

            const uint32_t bufA = ST + (s & 1) * BUFSZ;
#pragma unroll
            for (int ks = 0; ks < 2; ks++) {
                uint32_t ahi[2][4], alo[2][4];
                const uint32_t cA = (uint32_t)(((2 * ks + cbA) ^ swA) << 4);
#pragma unroll
                for (int mt = 0; mt < 2; mt++) {
                    ldsm4(ahi[mt], bufA + preA + mt * 1024 + cA);
                    ldsm4(alo[mt], bufA + 8192 + preA + mt * 1024 + cA);
                }
                const uint32_t cB = (uint32_t)(((2 * ks + cbB) ^ swB) << 4);
#pragma unroll
                for (int g = 0; g < 8; g++) {
                    uint32_t bh[4], bl[4];
                    ldsm4(bh, bufA + preBh + g * 1024 + cB);
                    ldsm4(bl, bufA + preBl + g * 1024 + cB);
#pragma unroll
                    for (int mt = 0; mt < 2; mt++) {
                        mma16816(acc[mt][2 * g],     ahi[mt], bh);
                        mma16816(acc[mt][2 * g + 1], ahi[mt], bh + 2);
                        mma16816(acc[mt][2 * g],     ahi[mt], bl);
                        mma16816(acc[mt][2 * g + 1], ahi[mt], bl + 2);
                        mma16816(acc[mt][2 * g],     alo[mt], bh);
                        mma16816(acc[mt][2 * g + 1], alo[mt], bh + 2);
                    }
                }
            }
            __syncthreads();
        }

        // fused epilogue for this n-chunk
#pragma unroll
        for (int mt = 0; mt < 2; mt++)
#pragma unroll
            for (int j = 0; j < 16; j++) {
                const int n = nc * 256 + wn * 128 + j * 8 + 2 * (lane & 3);
                const float b10 = b1s[n], b11 = b1s[n + 1];
                const float w20 = w2s[n], w21 = w2s[n + 1];
                float h0 = acc[mt][j][0] + b10;
                float h1 = acc[mt][j][1] + b11;
                float h2 = acc[mt][j][2] + b10;
                float h3 = acc[mt][j][3] + b11;
                const float K = 0.70710678118654752f;
                float g0 = 0.5f * h0 * (1.0f + erff(h0 * K));
                float g1 = 0.5f * h1 * (1.0f + erff(h1 * K));
                float g2 = 0.5f * h2 * (1.0f + erff(h2 * K));
                float g3 = 0.5f * h3 * (1.0f + erff(h3 * K));
                ya[mt][0] = fmaf(g0, w20, fmaf(g1, w21, ya[mt][0]));
                ya[mt][1] = fmaf(g2, w20, fmaf(g3, w21, ya[mt][1]));
            }
    }

    // reduce partial y across lane quads; rows: wm*32 + mt*16 + (lane>>2) + rr*8
#pragma unroll
    for (int mt = 0; mt < 2; mt++)
#pragma unroll
        for (int rr = 0; rr < 2; rr++) {
            float v = ya[mt][rr];
            v += __shfl_xor_sync(0xFFFFFFFF, v, 1);
            v += __shfl_xor_sync(0xFFFFFFFF, v, 2);
            if ((lane & 3) == 0) {
                int r = wm * 32 + mt * 16 + (lane >> 2) + rr * 8;
                red[r * 2 + wn] = v;
            }
        }
    __syncthreads();

    if (tid < TM) {
        float sv = red[tid * 2] + red[tid * 2 + 1] + __ldg(&b2g[t]);
        float y = fmaxf(sv, 0.f) + log1pf(expf(-fabsf(sv)));
        if (tid < rows) out[srow_sm[tid]] = y;
    }
}

// ---------------- launch ----------------
extern "C" void kernel_launch(void* const* d_in, const int* in_sizes, int n_in,
                              void* d_out, int out_size)
{
    const float* g  = (const float*)d_in[0];
    const void*  tv = d_in[1];
    const float* W1 = (const float*)d_in[2];
    const float* b1 = (const float*)d_in[3];
    const float* W2 = (const float*)d_in[4];
    const float* b2 = (const float*)d_in[5];
    float* out = (float*)d_out;

    cudaFuncSetAttribute(gemm_mma, cudaFuncAttributeMaxDynamicSharedMemorySize, SM_TOTAL);

    detect_kernel<<<1, 256>>>((const int*)tv);
    hist_kernel<<<(NB + 255) / 256, 256>>>(tv);
    plan_kernel<<<1, 1>>>();
    scatter_kernel<<<(NB + 255) / 256, 256>>>(tv);

    prep_g<<<NB * NE / 4 / 256, 256>>>(g);
    prep_w<<<NT * 8, 256>>>(W1);

    gemm_mma<<<MAXTILES, 256, SM_TOTAL>>>(b1, W2, b2, out);
}

// round 4
// speedup vs baseline: 1.7819x; 1.3081x over previous
#include <cuda_runtime.h>
#include <cuda_bf16.h>
#include <math.h>
#include <stdint.h>

#define NB 8192
#define NE 512
#define NT 32
#define TM 128
#define MAXTILES (NB/TM + NT)        // 96
#define NQ 8                         // N-chunks of 64 per tile
#define MAXCTAS (MAXTILES * NQ)      // 768

// ---------------- device scratch ----------------
__device__ int d_perm[NB];
__device__ int d_tile_tissue[MAXTILES];
__device__ int d_tile_start[MAXTILES];
__device__ int d_tile_rows[MAXTILES];
__device__ int d_ntiles;
__device__ float d_part[MAXCTAS * TM];

__device__ __nv_bfloat16 d_Ghi[NB * NE];
__device__ __nv_bfloat16 d_Glo[NB * NE];
__device__ __nv_bfloat16 d_WhiT[(size_t)NT * NE * NE];   // [t][n][k]
__device__ __nv_bfloat16 d_WloT[(size_t)NT * NE * NE];

// ---------------- PTX helpers (sm_80-level) ----------------
__device__ __forceinline__ uint32_t smem_u32(const void* p) {
    uint32_t a;
    asm("{ .reg .u64 t; cvta.to.shared.u64 t, %1; cvt.u32.u64 %0, t; }"
        : "=r"(a) : "l"(p));
    return a;
}
#define CP16(dst, src) \
    asm volatile("cp.async.cg.shared.global [%0], [%1], 16;" \
                 :: "r"(dst), "l"(src) : "memory")
#define CP_COMMIT() asm volatile("cp.async.commit_group;" ::: "memory")
#define CP_WAIT1()  asm volatile("cp.async.wait_group 1;" ::: "memory")
#define CP_WAIT0()  asm volatile("cp.async.wait_group 0;" ::: "memory")

__device__ __forceinline__ void ldsm4(uint32_t r[4], uint32_t addr) {
    asm volatile("ldmatrix.sync.aligned.m8n8.x4.shared.b16 {%0,%1,%2,%3}, [%4];"
                 : "=r"(r[0]), "=r"(r[1]), "=r"(r[2]), "=r"(r[3]) : "r"(addr));
}
__device__ __forceinline__ void mma16816(float d[4], const uint32_t a[4],
                                         const uint32_t b[2]) {
    asm volatile(
        "mma.sync.aligned.m16n8k16.row.col.f32.bf16.bf16.f32 "
        "{%0,%1,%2,%3}, {%4,%5,%6,%7}, {%8,%9}, {%0,%1,%2,%3};"
        : "+f"(d[0]), "+f"(d[1]), "+f"(d[2]), "+f"(d[3])
        : "r"(a[0]), "r"(a[1]), "r"(a[2]), "r"(a[3]), "r"(b[0]), "r"(b[1]));
}
__device__ __forceinline__ unsigned pack2(__nv_bfloat16 a, __nv_bfloat16 b) {
    return (unsigned)__bfloat16_as_ushort(a) | ((unsigned)__bfloat16_as_ushort(b) << 16);
}

// ---------------- ONE grouping kernel (single CTA) ----------------
__global__ void group_all(const int* tv32) {
    __shared__ int s_is64;
    __shared__ int cnt[NT], cur[NT];
    __shared__ int warpor[32];
    const int tid = threadIdx.x;

    int acc = 0;
    for (int i = tid; i < NB / 2; i += 1024) acc |= tv32[2 * i + 1];
#pragma unroll
    for (int o = 16; o; o >>= 1) acc |= __shfl_xor_sync(0xFFFFFFFF, acc, o);
    if ((tid & 31) == 0) warpor[tid >> 5] = acc;
    if (tid < NT) cnt[tid] = 0;
    __syncthreads();
    if (tid == 0) {
        int a = 0;
        for (int i = 0; i < 32; i++) a |= warpor[i];
        s_is64 = (a == 0);
    }
    __syncthreads();
    const int is64 = s_is64;

    for (int i = tid; i < NB; i += 1024) {
        int t = is64 ? (int)((const long long*)tv32)[i] : tv32[i];
        atomicAdd(&cnt[t], 1);
    }
    __syncthreads();
    if (tid == 0) {
        int off = 0, nt = 0;
        for (int t = 0; t < NT; t++) {
            int c = cnt[t];
            cur[t] = off;
            for (int s = 0; s < c; s += TM) {
                d_tile_tissue[nt] = t;
                d_tile_start[nt]  = off + s;
                d_tile_rows[nt]   = (c - s) < TM ? (c - s) : TM;
                nt++;
            }
            off += c;
        }
        d_ntiles = nt;
    }
    __syncthreads();
    for (int i = tid; i < NB; i += 1024) {
        int t = is64 ? (int)((const long long*)tv32)[i] : tv32[i];
        int p = atomicAdd(&cur[t], 1);
        d_perm[p] = i;
    }
}

// ---------------- prep: fp32 -> bf16 hi/lo ----------------
__global__ void prep_g(const float* __restrict__ g) {
    int i = blockIdx.x * 256 + threadIdx.x;
    float4 v = ((const float4*)g)[i];
    float x[4] = {v.x, v.y, v.z, v.w};
    __nv_bfloat16 hb[4], lb[4];
#pragma unroll
    for (int j = 0; j < 4; j++) {
        hb[j] = __float2bfloat16(x[j]);
        lb[j] = __float2bfloat16(x[j] - __bfloat162float(hb[j]));
    }
    ((uint2*)d_Ghi)[i] = make_uint2(pack2(hb[0], hb[1]), pack2(hb[2], hb[3]));
    ((uint2*)d_Glo)[i] = make_uint2(pack2(lb[0], lb[1]), pack2(lb[2], lb[3]));
}

// one 64x64 transpose chunk per block; grid = NT*8*8 = 2048
__global__ void prep_w(const float* __restrict__ W1) {
    const int bx = blockIdx.x;
    const int t  = bx >> 6;
    const int n0 = ((bx >> 3) & 7) * 64;
    const int k0 = (bx & 7) * 64;
    __shared__ float st[64][65];
    const size_t tb = (size_t)t * NE * NE;
#pragma unroll
    for (int rr = 0; rr < 4; rr++) {
        int idx = threadIdx.x + rr * 256;
        int k = idx >> 4;
        int nqc = (idx & 15) << 2;
        float4 v = *(const float4*)(W1 + tb + (size_t)(k0 + k) * NE + n0 + nqc);
        st[nqc + 0][k] = v.x; st[nqc + 1][k] = v.y;
        st[nqc + 2][k] = v.z; st[nqc + 3][k] = v.w;
    }
    __syncthreads();
    {
        int n  = threadIdx.x >> 2;
        int kq = (threadIdx.x & 3) << 4;
        unsigned hw[8], lw[8];
#pragma unroll
        for (int j = 0; j < 16; j += 2) {
            float x0 = st[n][kq + j], x1 = st[n][kq + j + 1];
            __nv_bfloat16 h0 = __float2bfloat16(x0), h1 = __float2bfloat16(x1);
            __nv_bfloat16 l0 = __float2bfloat16(x0 - __bfloat162float(h0));
            __nv_bfloat16 l1 = __float2bfloat16(x1 - __bfloat162float(h1));
            hw[j >> 1] = pack2(h0, h1);
            lw[j >> 1] = pack2(l0, l1);
        }
        size_t oo = tb + (size_t)(n0 + n) * NE + k0 + kq;
        *(uint4*)(d_WhiT + oo)     = make_uint4(hw[0], hw[1], hw[2], hw[3]);
        *(uint4*)(d_WhiT + oo + 8) = make_uint4(hw[4], hw[5], hw[6], hw[7]);
        *(uint4*)(d_WloT + oo)     = make_uint4(lw[0], lw[1], lw[2], lw[3]);
        *(uint4*)(d_WloT + oo + 8) = make_uint4(lw[4], lw[5], lw[6], lw[7]);
    }
}

// ---------------- mma.sync fused GEMM (M=128, N=64 per CTA) ----------------
// stage buf: Ahi 0..8K | Alo 8K..16K | Bhi 16K..20K | Blo 20K..24K
#define BUFSZ   24576
#define SM_TOTAL (2 * BUFSZ)

__global__ void __launch_bounds__(128, 3)
gemm_mma(const float* __restrict__ b1g, const float* __restrict__ W2g)
{
    extern __shared__ char smem[];
    const uint32_t ST = smem_u32(smem);
    const int tid = threadIdx.x, lane = tid & 31, wm = tid >> 5;

    const int b = blockIdx.x;
    const int tile = b >> 3, nq = b & 7;
    if (tile >= d_ntiles) return;
    const int t = d_tile_tissue[tile];
    const int start = d_tile_start[tile];
    const int rows  = d_tile_rows[tile];

    // per-thread gmem bases
    const int m = tid < rows ? tid : rows - 1;
    const size_t aoff = (size_t)d_perm[start + m] * NE;
    const __nv_bfloat16* pAhi = d_Ghi + aoff;
    const __nv_bfloat16* pAlo = d_Glo + aoff;
    const size_t wbase = (size_t)t * NE * NE + (size_t)(nq * 64 + (tid >> 1)) * NE;
    const __nv_bfloat16* pBhi = d_WhiT + wbase;
    const __nv_bfloat16* pBlo = d_WloT + wbase;

    // store-side addressing
    const uint32_t stA = ST + (uint32_t)tid * 64;
    const int swsA = (tid >> 1) & 3;
    const uint32_t stB = ST + 16384u + (uint32_t)(tid >> 1) * 64;
    const int swsB = (tid >> 2) & 3;
    const int cp = (tid & 1) * 2;

    // ldmatrix addressing (proven in R3)
    const int rA  = lane & 15;
    const int cbA = lane >> 4;
    const int swA = (rA >> 1) & 3;
    const uint32_t preA = (uint32_t)(wm * 32 + rA) * 64;
    const int rB  = (lane & 7) + ((lane >> 4) & 1) * 8;
    const int cbB = (lane >> 3) & 1;
    const int swB = ((lane & 7) >> 1) & 3;
    const uint32_t preB = (uint32_t)rB * 64;

    float acc[2][8][4];
#pragma unroll
    for (int mt = 0; mt < 2; mt++)
#pragma unroll
        for (int j = 0; j < 8; j++)
#pragma unroll
            for (int q = 0; q < 4; q++) acc[mt][j][q] = 0.f;

    // stage loader
    auto stage_load = [&](int s) {
        const uint32_t bufb = ST == 0 ? 0 : 0;  // placate compiler; real base below
        const uint32_t off = (uint32_t)(s & 1) * BUFSZ;
        const int k0 = s * 32;
        (void)bufb;
#pragma unroll
        for (int c = 0; c < 4; c++) {
            uint32_t d = stA + off + (uint32_t)((c ^ swsA) << 4);
            CP16(d,        pAhi + k0 + c * 8);
            CP16(d + 8192, pAlo + k0 + c * 8);
        }
#pragma unroll
        for (int c = cp; c < cp + 2; c++) {
            uint32_t d = stB + off + (uint32_t)((c ^ swsB) << 4);
            CP16(d,        pBhi + k0 + c * 8);
            CP16(d + 4096, pBlo + k0 + c * 8);
        }
    };

    stage_load(0);
    CP_COMMIT();

    for (int s = 0; s < 16; s++) {
        if (s < 15) {
            stage_load(s + 1);
            CP_COMMIT();
            CP_WAIT1();
        } else {
            CP_WAIT0();
        }
        __syncthreads();

        const uint32_t bufA = ST + (uint32_t)(s & 1) * BUFSZ;
#pragma unroll
        for (int ks = 0; ks < 2; ks++) {
            uint32_t ahi[2][4], alo[2][4];
            const uint32_t cA = (uint32_t)(((2 * ks + cbA) ^ swA) << 4);
#pragma unroll
            for (int mt = 0; mt < 2; mt++) {
                ldsm4(ahi[mt], bufA + preA + mt * 1024 + cA);
                ldsm4(alo[mt], bufA + 8192 + preA + mt * 1024 + cA);
            }
            const uint32_t cB = (uint32_t)(((2 * ks + cbB) ^ swB) << 4);
#pragma unroll
            for (int g = 0; g < 4; g++) {
                uint32_t bh[4], bl[4];
                ldsm4(bh, bufA + 16384 + preB + g * 1024 + cB);
                ldsm4(bl, bufA + 20480 + preB + g * 1024 + cB);
#pragma unroll
                for (int mt = 0; mt < 2; mt++) {
                    mma16816(acc[mt][2 * g],     ahi[mt], bh);
                    mma16816(acc[mt][2 * g + 1], ahi[mt], bh + 2);
                    mma16816(acc[mt][2 * g],     ahi[mt], bl);
                    mma16816(acc[mt][2 * g + 1], ahi[mt], bl + 2);
                    mma16816(acc[mt][2 * g],     alo[mt], bh);
                    mma16816(acc[mt][2 * g + 1], alo[mt], bh + 2);
                }
            }
        }
        __syncthreads();
    }

    // fused epilogue: +b1 -> gelu -> *W2 -> partial row sums
    float ya[2][2] = {{0.f, 0.f}, {0.f, 0.f}};
#pragma unroll
    for (int mt = 0; mt < 2; mt++)
#pragma unroll
        for (int j = 0; j < 8; j++) {
            const int n = nq * 64 + j * 8 + 2 * (lane & 3);
            const float b10 = __ldg(&b1g[t * NE + n]);
            const float b11 = __ldg(&b1g[t * NE + n + 1]);
            const float w20 = __ldg(&W2g[t * NE + n]);
            const float w21 = __ldg(&W2g[t * NE + n + 1]);
            float h0 = acc[mt][j][0] + b10;
            float h1 = acc[mt][j][1] + b11;
            float h2 = acc[mt][j][2] + b10;
            float h3 = acc[mt][j][3] + b11;
            const float K = 0.70710678118654752f;
            float g0 = 0.5f * h0 * (1.0f + erff(h0 * K));
            float g1 = 0.5f * h1 * (1.0f + erff(h1 * K));
            float g2 = 0.5f * h2 * (1.0f + erff(h2 * K));
            float g3 = 0.5f * h3 * (1.0f + erff(h3 * K));
            ya[mt][0] = fmaf(g0, w20, fmaf(g1, w21, ya[mt][0]));
            ya[mt][1] = fmaf(g2, w20, fmaf(g3, w21, ya[mt][1]));
        }

#pragma unroll
    for (int mt = 0; mt < 2; mt++)
#pragma unroll
        for (int rr = 0; rr < 2; rr++) {
            float v = ya[mt][rr];
            v += __shfl_xor_sync(0xFFFFFFFF, v, 1);
            v += __shfl_xor_sync(0xFFFFFFFF, v, 2);
            if ((lane & 3) == 0) {
                int r = wm * 32 + mt * 16 + (lane >> 2) + rr * 8;
                d_part[b * TM + r] = v;
            }
        }
}

// ---------------- finale: sum 8 partials + b2, softplus, scatter ----------------
__global__ void finale(const float* __restrict__ b2g, float* __restrict__ out) {
    const int tile = blockIdx.x;
    if (tile >= d_ntiles) return;
    const int tid = threadIdx.x;
    const int t = d_tile_tissue[tile];
    const int start = d_tile_start[tile];
    const int rows  = d_tile_rows[tile];
    if (tid < rows) {
        float s = 0.f;
#pragma unroll
        for (int q = 0; q < NQ; q++)
            s += d_part[(tile * NQ + q) * TM + tid];
        s += __ldg(&b2g[t]);
        float y = fmaxf(s, 0.f) + log1pf(expf(-fabsf(s)));
        out[d_perm[start + tid]] = y;
    }
}

// ---------------- launch ----------------
extern "C" void kernel_launch(void* const* d_in, const int* in_sizes, int n_in,
                              void* d_out, int out_size)
{
    const float* g  = (const float*)d_in[0];
    const void*  tv = d_in[1];
    const float* W1 = (const float*)d_in[2];
    const float* b1 = (const float*)d_in[3];
    const float* W2 = (const float*)d_in[4];
    const float* b2 = (const float*)d_in[5];
    float* out = (float*)d_out;

    cudaFuncSetAttribute(gemm_mma, cudaFuncAttributeMaxDynamicSharedMemorySize, SM_TOTAL);

    group_all<<<1, 1024>>>((const int*)tv);
    prep_g<<<NB * NE / 4 / 256, 256>>>(g);
    prep_w<<<NT * 64, 256>>>(W1);
    gemm_mma<<<MAXCTAS, 128, SM_TOTAL>>>(b1, W2);
    finale<<<MAXTILES, TM>>>(b2, out);
}